// round 1
// baseline (speedup 1.0000x reference)
#include <cuda_runtime.h>
#include <math.h>

#define SEQ 2048
#define HID 1024
#define NCTA_SCAN 64
#define ROWS_PER_CTA 16   // HID / NCTA_SCAN

// Scratch (device globals: no allocation allowed in kernel_launch)
__device__ float g_pre0[SEQ * HID];     // 8 MB: x@W_ih^T + internal[0] + b
__device__ float g_hbuf[2][HID];        // double-buffered recurrent state
__device__ unsigned g_count = 0;        // grid barrier (self-resetting)
__device__ unsigned g_sense = 0;

// ---------------------------------------------------------------------------
// Tiled fp32 GEMM:  C[m][n] = op( sum_k A[m][k]*B[n][k] + addm[m][n] + b1[n] + b2[n] )
// BM=BN=128, BK=16, 256 threads, 8x8 microtile (split 4+4 with 64 offset for
// conflict-friendly LDS.128). M,N,K assumed multiples of 128/128/16.
// ---------------------------------------------------------------------------
__global__ void __launch_bounds__(256, 1)
gemm_nt(const float* __restrict__ A, const float* __restrict__ B,
        const float* __restrict__ addm,
        const float* __restrict__ bias1, const float* __restrict__ bias2,
        float* __restrict__ C, int M, int N, int K, int do_tanh)
{
    __shared__ float As[16][128];
    __shared__ float Bs[16][128];

    const int tid = threadIdx.x;
    const int tx = tid & 15;
    const int ty = tid >> 4;
    const int m0 = blockIdx.y * 128;
    const int n0 = blockIdx.x * 128;

    const int lr = tid >> 2;          // 0..63 (row within half-tile)
    const int lk = (tid & 3) << 2;    // 0,4,8,12

    const float* Ap = A + (size_t)(m0 + lr) * K + lk;
    const float* Bp = B + (size_t)(n0 + lr) * K + lk;

    float acc[8][8];
    #pragma unroll
    for (int i = 0; i < 8; i++)
        #pragma unroll
        for (int j = 0; j < 8; j++) acc[i][j] = 0.f;

    for (int k0 = 0; k0 < K; k0 += 16) {
        float4 a0 = *(const float4*)(Ap + k0);
        float4 a1 = *(const float4*)(Ap + (size_t)64 * K + k0);
        float4 b0 = *(const float4*)(Bp + k0);
        float4 b1 = *(const float4*)(Bp + (size_t)64 * K + k0);
        __syncthreads();   // previous iteration's LDS reads complete
        As[lk + 0][lr] = a0.x; As[lk + 1][lr] = a0.y;
        As[lk + 2][lr] = a0.z; As[lk + 3][lr] = a0.w;
        As[lk + 0][lr + 64] = a1.x; As[lk + 1][lr + 64] = a1.y;
        As[lk + 2][lr + 64] = a1.z; As[lk + 3][lr + 64] = a1.w;
        Bs[lk + 0][lr] = b0.x; Bs[lk + 1][lr] = b0.y;
        Bs[lk + 2][lr] = b0.z; Bs[lk + 3][lr] = b0.w;
        Bs[lk + 0][lr + 64] = b1.x; Bs[lk + 1][lr + 64] = b1.y;
        Bs[lk + 2][lr + 64] = b1.z; Bs[lk + 3][lr + 64] = b1.w;
        __syncthreads();

        #pragma unroll
        for (int k = 0; k < 16; k++) {
            float ar[8], br[8];
            *(float4*)(ar)     = *(const float4*)&As[k][ty * 4];
            *(float4*)(ar + 4) = *(const float4*)&As[k][ty * 4 + 64];
            *(float4*)(br)     = *(const float4*)&Bs[k][tx * 4];
            *(float4*)(br + 4) = *(const float4*)&Bs[k][tx * 4 + 64];
            #pragma unroll
            for (int i = 0; i < 8; i++)
                #pragma unroll
                for (int j = 0; j < 8; j++)
                    acc[i][j] += ar[i] * br[j];
        }
    }

    #pragma unroll
    for (int i = 0; i < 8; i++) {
        const int m = m0 + ((i < 4) ? (ty * 4 + i) : (64 + ty * 4 + i - 4));
        #pragma unroll
        for (int j = 0; j < 8; j++) {
            const int n = n0 + ((j < 4) ? (tx * 4 + j) : (64 + tx * 4 + j - 4));
            float v = acc[i][j] + addm[(size_t)m * N + n] + bias1[n] + bias2[n];
            if (do_tanh) v = tanhf(v);
            C[(size_t)m * N + n] = v;
        }
    }
}

// ---------------------------------------------------------------------------
// Sequential scan: h_t = tanh(pre0[t] + h_{t-1} @ W_hh^T), 2048 steps.
// 64 persistent CTAs x 256 threads. Each CTA owns 16 output rows; W_hh rows
// live in REGISTERS (64 floats/thread, loaded once). h broadcast via smem.
// Per-step sense-reversing atomic grid barrier (state self-resets: 2048 flips).
// ---------------------------------------------------------------------------
__global__ void __launch_bounds__(256, 1)
scan_kernel(const float* __restrict__ pre0, const float* __restrict__ state,
            const float* __restrict__ W, float* __restrict__ out0,
            float* __restrict__ hT)
{
    const int tid = threadIdx.x;
    const int l = tid & 15;              // lane within row-group: cols l*4 + k*64
    const int r = tid >> 4;              // row within CTA
    const int row = blockIdx.x * ROWS_PER_CTA + r;

    // Stage this thread's W_hh slice into registers (constant across steps).
    float4 w[16];
    const float4* Wrow = (const float4*)(W + (size_t)row * HID);
    #pragma unroll
    for (int k = 0; k < 16; k++) w[k] = Wrow[l + k * 16];

    __shared__ float hs[HID];
    const float* hprev = state;
    unsigned sense = 0;

    for (int t = 0; t < SEQ; t++) {
        // Issue pre0 load early (independent of h) to hide its latency.
        float pre = 0.f;
        if (l == 0) pre = __ldg(pre0 + (size_t)t * HID + row);

        // Broadcast h_{t-1} into smem (256 threads x float4 = 1024 floats).
        float4 hv = ((const float4*)hprev)[tid];
        ((float4*)hs)[tid] = hv;
        __syncthreads();

        float s0 = 0.f, s1 = 0.f, s2 = 0.f, s3 = 0.f;
        #pragma unroll
        for (int k = 0; k < 16; k++) {
            float4 hh = *(const float4*)(hs + l * 4 + k * 64);
            s0 += w[k].x * hh.x;
            s1 += w[k].y * hh.y;
            s2 += w[k].z * hh.z;
            s3 += w[k].w * hh.w;
        }
        float sum = (s0 + s1) + (s2 + s3);
        #pragma unroll
        for (int off = 8; off; off >>= 1)
            sum += __shfl_xor_sync(0xffffffffu, sum, off, 16);

        float* cur = g_hbuf[t & 1];
        if (l == 0) {
            const float hnew = tanhf(pre + sum);
            cur[row] = hnew;
            out0[(size_t)t * HID + row] = hnew;
            if (hT && t == SEQ - 1) hT[row] = hnew;
            __threadfence();               // publish before barrier arrival
        }
        __syncthreads();

        // Grid barrier (sense-reversing, centralized).
        if (tid == 0) {
            sense ^= 1u;
            const unsigned old = atomicAdd(&g_count, 1u);
            if (old == NCTA_SCAN - 1) {
                g_count = 0;               // all arrived; safe plain store
                __threadfence();
                atomicExch(&g_sense, sense);
            } else {
                while (*((volatile unsigned*)&g_sense) != sense) { }
            }
            __threadfence();               // acquire for upcoming g_hbuf reads
        }
        __syncthreads();

        hprev = cur;
    }
}

extern "C" void kernel_launch(void* const* d_in, const int* in_sizes, int n_in,
                              void* d_out, int out_size)
{
    const float* x        = (const float*)d_in[0];   // [1, 2048, 1024]
    const float* internal = (const float*)d_in[1];   // [8, 2048, 1024]
    const float* state    = (const float*)d_in[2];   // [1, 1, 1024]
    const float* W_ih     = (const float*)d_in[3];   // [1024, 1024]
    const float* W_hh     = (const float*)d_in[4];   // [1024, 1024]
    const float* b_ih     = (const float*)d_in[5];   // [1024]
    const float* b_hh     = (const float*)d_in[6];   // [1024]
    float* out = (float*)d_out;                      // [8, 2048, 1024] (+ hT [1024])

    (void)in_sizes; (void)n_in;

    float* pre0 = nullptr;
    cudaGetSymbolAddress((void**)&pre0, g_pre0);     // host-side, capture-safe

    const dim3 grid(HID / 128, SEQ / 128);           // (8, 16) = 128 CTAs

    // Phase A: pre0 = x @ W_ih^T + internal[0] + b_ih + b_hh   (no tanh)
    gemm_nt<<<grid, 256>>>(x, W_ih, internal, b_ih, b_hh, pre0,
                           SEQ, HID, HID, 0);

    // Phase B: sequential base recurrence -> out[0], and hT tail if present.
    float* hT = nullptr;
    if (out_size >= 8 * SEQ * HID + HID) hT = out + (size_t)8 * SEQ * HID;
    scan_kernel<<<NCTA_SCAN, 256>>>(pre0, state, W_hh, out, hT);

    // Phase C: theta chains, batched over seq:
    //   out[k] = tanh(out[k-1] @ W_hh^T + internal[k] + b_ih + b_hh), k=1..7
    for (int th = 1; th <= 7; th++) {
        gemm_nt<<<grid, 256>>>(out + (size_t)(th - 1) * SEQ * HID, W_hh,
                               internal + (size_t)th * SEQ * HID, b_ih, b_hh,
                               out + (size_t)th * SEQ * HID,
                               SEQ, HID, HID, 1);
    }
}

// round 2
// speedup vs baseline: 1.3007x; 1.3007x over previous
#include <cuda_runtime.h>
#include <math.h>

#define SEQ 2048
#define HID 1024
#define NCTA_SCAN 64
#define ROWS_PER_CTA 16   // HID / NCTA_SCAN

// Scratch (device globals: no allocation allowed in kernel_launch)
__device__ float g_pre0[SEQ * HID];     // 8 MB: x@W_ih^T + internal[0] + b
__device__ float g_hbuf[2][HID];        // double-buffered recurrent state

// Per-CTA publish flags, one 128B line each (no false sharing, no contention)
struct alignas(128) PadFlag { unsigned v; unsigned pad[31]; };
__device__ PadFlag g_flag[NCTA_SCAN];

__global__ void init_flags_kernel() {
    if (threadIdx.x < NCTA_SCAN) g_flag[threadIdx.x].v = 0u;
}

// ---------------------------------------------------------------------------
// Tiled fp32 GEMM:  C[m][n] = op( sum_k A[m][k]*B[n][k] + addm[m][n] + b1[n] + b2[n] )
// BM=BN=128, BK=16, 256 threads, 8x8 microtile.
// ---------------------------------------------------------------------------
__global__ void __launch_bounds__(256, 1)
gemm_nt(const float* __restrict__ A, const float* __restrict__ B,
        const float* __restrict__ addm,
        const float* __restrict__ bias1, const float* __restrict__ bias2,
        float* __restrict__ C, int M, int N, int K, int do_tanh)
{
    __shared__ float As[16][128];
    __shared__ float Bs[16][128];

    const int tid = threadIdx.x;
    const int tx = tid & 15;
    const int ty = tid >> 4;
    const int m0 = blockIdx.y * 128;
    const int n0 = blockIdx.x * 128;

    const int lr = tid >> 2;          // 0..63 (row within half-tile)
    const int lk = (tid & 3) << 2;    // 0,4,8,12

    const float* Ap = A + (size_t)(m0 + lr) * K + lk;
    const float* Bp = B + (size_t)(n0 + lr) * K + lk;

    float acc[8][8];
    #pragma unroll
    for (int i = 0; i < 8; i++)
        #pragma unroll
        for (int j = 0; j < 8; j++) acc[i][j] = 0.f;

    for (int k0 = 0; k0 < K; k0 += 16) {
        float4 a0 = *(const float4*)(Ap + k0);
        float4 a1 = *(const float4*)(Ap + (size_t)64 * K + k0);
        float4 b0 = *(const float4*)(Bp + k0);
        float4 b1 = *(const float4*)(Bp + (size_t)64 * K + k0);
        __syncthreads();   // previous iteration's LDS reads complete
        As[lk + 0][lr] = a0.x; As[lk + 1][lr] = a0.y;
        As[lk + 2][lr] = a0.z; As[lk + 3][lr] = a0.w;
        As[lk + 0][lr + 64] = a1.x; As[lk + 1][lr + 64] = a1.y;
        As[lk + 2][lr + 64] = a1.z; As[lk + 3][lr + 64] = a1.w;
        Bs[lk + 0][lr] = b0.x; Bs[lk + 1][lr] = b0.y;
        Bs[lk + 2][lr] = b0.z; Bs[lk + 3][lr] = b0.w;
        Bs[lk + 0][lr + 64] = b1.x; Bs[lk + 1][lr + 64] = b1.y;
        Bs[lk + 2][lr + 64] = b1.z; Bs[lk + 3][lr + 64] = b1.w;
        __syncthreads();

        #pragma unroll
        for (int k = 0; k < 16; k++) {
            float ar[8], br[8];
            *(float4*)(ar)     = *(const float4*)&As[k][ty * 4];
            *(float4*)(ar + 4) = *(const float4*)&As[k][ty * 4 + 64];
            *(float4*)(br)     = *(const float4*)&Bs[k][tx * 4];
            *(float4*)(br + 4) = *(const float4*)&Bs[k][tx * 4 + 64];
            #pragma unroll
            for (int i = 0; i < 8; i++)
                #pragma unroll
                for (int j = 0; j < 8; j++)
                    acc[i][j] += ar[i] * br[j];
        }
    }

    #pragma unroll
    for (int i = 0; i < 8; i++) {
        const int m = m0 + ((i < 4) ? (ty * 4 + i) : (64 + ty * 4 + i - 4));
        #pragma unroll
        for (int j = 0; j < 8; j++) {
            const int n = n0 + ((j < 4) ? (tx * 4 + j) : (64 + tx * 4 + j - 4));
            float v = acc[i][j] + addm[(size_t)m * N + n] + bias1[n] + bias2[n];
            if (do_tanh) v = tanhf(v);
            C[(size_t)m * N + n] = v;
        }
    }
}

// ---------------------------------------------------------------------------
// Sequential scan: h_t = tanh(pre0[t] + h_{t-1} @ W_hh^T), 2048 steps.
// 64 persistent CTAs x 256 threads. Each CTA owns 16 output rows; W_hh rows
// live in REGISTERS (64 floats/thread, loaded once). h broadcast via smem.
//
// Synchronization: distributed per-CTA flags. Producer thread 0 writes its
// 16-float slice (4x STG.128) then st.release.gpu its own flag. Consumers
// poll 64 distinct flag lines with ld.acquire.gpu. NO threadfence
// (=> no CCTL.IVALL L1 flush), NO shared atomic counter, NO shared spin line.
// h is read with __ldcg (L2) since L1 is never invalidated.
// ---------------------------------------------------------------------------
__global__ void __launch_bounds__(256, 1)
scan_kernel(const float* __restrict__ pre0, const float* __restrict__ state,
            const float* __restrict__ W, float* __restrict__ out0,
            float* __restrict__ hT)
{
    const int tid = threadIdx.x;
    const int l = tid & 15;              // lane within row-group: cols l*4 + k*64
    const int r = tid >> 4;              // row within CTA
    const int row = blockIdx.x * ROWS_PER_CTA + r;

    // Stage this thread's W_hh slice into registers (constant across steps).
    float4 w[16];
    const float4* Wrow = (const float4*)(W + (size_t)row * HID);
    #pragma unroll
    for (int k = 0; k < 16; k++) w[k] = Wrow[l + k * 16];

    __shared__ float hs[HID];
    __shared__ float hn[ROWS_PER_CTA];

    for (int t = 0; t < SEQ; t++) {
        // Prefetch pre0 (independent of flags; overlaps the poll below).
        float pre = 0.f;
        if (l == 0) pre = __ldg(pre0 + (size_t)t * HID + row);

        // Wait until every CTA has published step t-1 (flag value == t).
        if (t > 0 && tid < NCTA_SCAN) {
            const unsigned* fp = &g_flag[tid].v;
            unsigned v;
            do {
                asm volatile("ld.acquire.gpu.global.u32 %0, [%1];"
                             : "=r"(v) : "l"(fp) : "memory");
            } while (v < (unsigned)t);
        }
        __syncthreads();   // flag-pass + protects hs from previous iteration

        // Broadcast h_{t-1} into smem (256 threads x float4 = 1024 floats).
        // __ldcg: must bypass L1 (nothing invalidates it anymore).
        const float* hsrc = (t == 0) ? state : g_hbuf[(t - 1) & 1];
        float4 hv = __ldcg((const float4*)hsrc + tid);
        ((float4*)hs)[tid] = hv;
        __syncthreads();

        float s0 = 0.f, s1 = 0.f, s2 = 0.f, s3 = 0.f;
        #pragma unroll
        for (int k = 0; k < 16; k++) {
            float4 hh = *(const float4*)(hs + l * 4 + k * 64);
            s0 += w[k].x * hh.x;
            s1 += w[k].y * hh.y;
            s2 += w[k].z * hh.z;
            s3 += w[k].w * hh.w;
        }
        float sum = (s0 + s1) + (s2 + s3);
        #pragma unroll
        for (int off = 8; off; off >>= 1)
            sum += __shfl_xor_sync(0xffffffffu, sum, off, 16);

        if (l == 0) {
            const float hnew = tanhf(pre + sum);
            hn[r] = hnew;                         // stage for single-thread publish
            out0[(size_t)t * HID + row] = hnew;   // off critical path
            if (hT && t == SEQ - 1) hT[row] = hnew;
        }
        __syncthreads();

        // Single-thread publish: slice store + release flag (clean ordering).
        if (tid == 0) {
            float* dst = g_hbuf[t & 1] + blockIdx.x * ROWS_PER_CTA;
            float4 v0 = *(const float4*)&hn[0];
            float4 v1 = *(const float4*)&hn[4];
            float4 v2 = *(const float4*)&hn[8];
            float4 v3 = *(const float4*)&hn[12];
            ((float4*)dst)[0] = v0;
            ((float4*)dst)[1] = v1;
            ((float4*)dst)[2] = v2;
            ((float4*)dst)[3] = v3;
            asm volatile("st.release.gpu.global.u32 [%0], %1;"
                         :: "l"(&g_flag[blockIdx.x].v), "r"((unsigned)(t + 1))
                         : "memory");
        }
        // No trailing syncthreads needed: next iteration's poll+sync protects hs.
    }
}

extern "C" void kernel_launch(void* const* d_in, const int* in_sizes, int n_in,
                              void* d_out, int out_size)
{
    const float* x        = (const float*)d_in[0];   // [1, 2048, 1024]
    const float* internal = (const float*)d_in[1];   // [8, 2048, 1024]
    const float* state    = (const float*)d_in[2];   // [1, 1, 1024]
    const float* W_ih     = (const float*)d_in[3];   // [1024, 1024]
    const float* W_hh     = (const float*)d_in[4];   // [1024, 1024]
    const float* b_ih     = (const float*)d_in[5];   // [1024]
    const float* b_hh     = (const float*)d_in[6];   // [1024]
    float* out = (float*)d_out;                      // [8, 2048, 1024] (+ hT [1024])

    (void)in_sizes; (void)n_in;

    float* pre0 = nullptr;
    cudaGetSymbolAddress((void**)&pre0, g_pre0);     // host-side, capture-safe

    const dim3 grid(HID / 128, SEQ / 128);           // (8, 16) = 128 CTAs

    // Reset flags for this launch (graph replays reuse device globals).
    init_flags_kernel<<<1, 64>>>();

    // Phase A: pre0 = x @ W_ih^T + internal[0] + b_ih + b_hh   (no tanh)
    gemm_nt<<<grid, 256>>>(x, W_ih, internal, b_ih, b_hh, pre0,
                           SEQ, HID, HID, 0);

    // Phase B: sequential base recurrence -> out[0], and hT tail if present.
    float* hT = nullptr;
    if (out_size >= 8 * SEQ * HID + HID) hT = out + (size_t)8 * SEQ * HID;
    scan_kernel<<<NCTA_SCAN, 256>>>(pre0, state, W_hh, out, hT);

    // Phase C: theta chains, batched over seq:
    //   out[k] = tanh(out[k-1] @ W_hh^T + internal[k] + b_ih + b_hh), k=1..7
    for (int th = 1; th <= 7; th++) {
        gemm_nt<<<grid, 256>>>(out + (size_t)(th - 1) * SEQ * HID, W_hh,
                               internal + (size_t)th * SEQ * HID, b_ih, b_hh,
                               out + (size_t)th * SEQ * HID,
                               SEQ, HID, HID, 1);
    }
}